// round 1
// baseline (speedup 1.0000x reference)
#include <cuda_runtime.h>
#include <math.h>

#define SS 3
#define BB 4
#define CC 256
#define HW 4096
#define NHh 8
#define HDd 32
#define EPSf 1e-5f

// ---------------- scratch (device globals; no allocations allowed) ----------
__device__ float g_pooled[BB*SS*CC];
__device__ float g_wmix[BB*SS];
__device__ float g_q [SS*BB*CC*HW];
__device__ float g_k [SS*BB*CC*HW];
__device__ float g_v [SS*BB*CC*HW];
__device__ float g_qt[SS*BB*CC*HW];
__device__ float g_kt[SS*BB*CC*HW];
__device__ float g_vt[SS*BB*CC*HW];
__device__ float g_o [SS*BB*CC*HW];
__device__ float g_integr[BB*CC*HW];
__device__ float g_y2[BB*CC*HW];

__device__ __forceinline__ float gelu_f(float x){
    return 0.5f * x * (1.0f + erff(x * 0.70710678118654752f));
}

// ---------------- stage 1: spatial mean pool --------------------------------
__global__ void k_pool(const float* __restrict__ x){
    int id = blockIdx.x;                  // s*(BB*CC) + b*CC + c
    int c = id & 255;
    int b = (id >> 8) & 3;
    int s = id >> 10;
    const float* p = x + (size_t)((s*BB+b)*CC + c) * HW;
    float sum = 0.f;
    for(int i = threadIdx.x; i < HW; i += 256) sum += p[i];
    __shared__ float red[8];
    #pragma unroll
    for(int o = 16; o > 0; o >>= 1) sum += __shfl_down_sync(0xffffffffu, sum, o);
    if((threadIdx.x & 31) == 0) red[threadIdx.x >> 5] = sum;
    __syncthreads();
    if(threadIdx.x == 0){
        float t = 0.f;
        #pragma unroll
        for(int i = 0; i < 8; i++) t += red[i];
        g_pooled[(b*SS + s)*CC + c] = t * (1.0f / HW);
    }
}

// ---------------- stage 2: importance MLP + softmax weights -----------------
__global__ void k_imp(const float* __restrict__ iw1, const float* __restrict__ ib1,
                      const float* __restrict__ iw2, const float* __restrict__ ib2){
    __shared__ float h[BB][CC];
    __shared__ float lg[BB][SS];
    int t = threadIdx.x;                  // 256 threads
    for(int b = 0; b < BB; b++){
        float acc = ib1[t];
        const float4* pw = (const float4*)(iw1 + t * (SS*CC));
        const float4* pp = (const float4*)(g_pooled + b * (SS*CC));
        #pragma unroll 4
        for(int i = 0; i < (SS*CC)/4; i++){
            float4 a = pw[i], c = pp[i];
            acc += a.x*c.x + a.y*c.y + a.z*c.z + a.w*c.w;
        }
        h[b][t] = gelu_f(acc);
    }
    __syncthreads();
    if(t < BB*SS){
        int b = t / SS, s = t % SS;
        float acc = ib2[s];
        for(int c = 0; c < CC; c++) acc += h[b][c] * iw2[s*CC + c];
        lg[b][s] = acc;
    }
    __syncthreads();
    if(t < BB){
        float m  = fmaxf(lg[t][0], fmaxf(lg[t][1], lg[t][2]));
        float e0 = expf(lg[t][0]-m), e1 = expf(lg[t][1]-m), e2 = expf(lg[t][2]-m);
        float inv = 1.0f / (e0 + e1 + e2);
        g_wmix[t*SS+0] = e0*inv; g_wmix[t*SS+1] = e1*inv; g_wmix[t*SS+2] = e2*inv;
    }
}

// ---------------- shared GEMM tile geometry ---------------------------------
// 128(M: out-channels) x 128(N: pixels) tile, BK=16, 256 threads, 8x8 micro-tile.

// stage 3: q/k/v projection GEMMs + BN + gelu
__global__ __launch_bounds__(256,2) void k_proj(
    const float* __restrict__ x,
    const float* __restrict__ Wq, const float* __restrict__ bq, const float* __restrict__ bnq,
    const float* __restrict__ Wk_, const float* __restrict__ bk_, const float* __restrict__ bnk,
    const float* __restrict__ Wv, const float* __restrict__ bv, const float* __restrict__ bnv)
{
    int z = blockIdx.z;
    int which = z / 12;
    int s = (z % 12) >> 2;
    int b = z & 3;
    const float *W, *bias, *bn; float* out;
    if(which == 0){ W = Wq;  bias = bq;  bn = bnq; out = g_q; }
    else if(which == 1){ W = Wk_; bias = bk_; bn = bnk; out = g_k; }
    else { W = Wv; bias = bv; bn = bnv; out = g_v; }
    W += s * CC * CC;
    const float* X = x   + (size_t)(s*BB+b)*CC*HW;
    float*       O = out + (size_t)(s*BB+b)*CC*HW;

    int m0 = blockIdx.y * 128;
    int n0 = blockIdx.x * 128;

    __shared__ float Ws[16][128];
    __shared__ float Xs[16][128];
    float acc[8][8];
    #pragma unroll
    for(int i=0;i<8;i++){ 
        #pragma unroll
        for(int j=0;j<8;j++) acc[i][j]=0.f; }

    int tid = threadIdx.x;
    int lm = tid >> 1, lk8 = (tid & 1) * 8;
    int xk = tid >> 4, xn8 = (tid & 15) * 8;
    int tmr = (tid >> 4) * 8, tnr = (tid & 15) * 8;

    for(int k0 = 0; k0 < CC; k0 += 16){
        float4 w0 = *(const float4*)&W[(m0+lm)*CC + k0 + lk8];
        float4 w1 = *(const float4*)&W[(m0+lm)*CC + k0 + lk8 + 4];
        Ws[lk8+0][lm]=w0.x; Ws[lk8+1][lm]=w0.y; Ws[lk8+2][lm]=w0.z; Ws[lk8+3][lm]=w0.w;
        Ws[lk8+4][lm]=w1.x; Ws[lk8+5][lm]=w1.y; Ws[lk8+6][lm]=w1.z; Ws[lk8+7][lm]=w1.w;
        const float* src = X + (size_t)(k0+xk)*HW + n0 + xn8;
        *(float4*)&Xs[xk][xn8]   = *(const float4*)(src);
        *(float4*)&Xs[xk][xn8+4] = *(const float4*)(src+4);
        __syncthreads();
        #pragma unroll
        for(int k = 0; k < 16; k++){
            float a[8], xr[8];
            *(float4*)&a[0] = *(float4*)&Ws[k][tmr];
            *(float4*)&a[4] = *(float4*)&Ws[k][tmr+4];
            *(float4*)&xr[0] = *(float4*)&Xs[k][tnr];
            *(float4*)&xr[4] = *(float4*)&Xs[k][tnr+4];
            #pragma unroll
            for(int i=0;i<8;i++)
                #pragma unroll
                for(int j=0;j<8;j++) acc[i][j] += a[i]*xr[j];
        }
        __syncthreads();
    }
    #pragma unroll
    for(int i = 0; i < 8; i++){
        int oc = m0 + tmr + i;
        float g  = bn[(s*4+0)*CC+oc];
        float be = bn[(s*4+1)*CC+oc];
        float mu = bn[(s*4+2)*CC+oc];
        float vr = bn[(s*4+3)*CC+oc];
        float sc = g * rsqrtf(vr + EPSf);
        float bi = bias[s*CC+oc];
        float* op = O + (size_t)oc*HW + n0 + tnr;
        #pragma unroll
        for(int j = 0; j < 8; j++){
            float y = acc[i][j] + bi;
            y = (y - mu)*sc + be;
            op[j] = gelu_f(y);
        }
    }
}

// stage 4: attn_in projections (q/k/v token projection)
__global__ __launch_bounds__(256,2) void k_attnin(const float* __restrict__ aiw,
                                                  const float* __restrict__ aib)
{
    int z = blockIdx.z;
    int which = z / 12;
    int s = (z % 12) >> 2;
    int b = z & 3;
    const float* W = aiw + which * CC * CC;
    const float* bias = aib + which * CC;
    const float* Xg; float* Og;
    if(which == 0){ Xg = g_q; Og = g_qt; }
    else if(which == 1){ Xg = g_k; Og = g_kt; }
    else { Xg = g_v; Og = g_vt; }
    const float* X = Xg + (size_t)(s*BB+b)*CC*HW;
    float*       O = Og + (size_t)(s*BB+b)*CC*HW;

    int m0 = blockIdx.y * 128;
    int n0 = blockIdx.x * 128;

    __shared__ float Ws[16][128];
    __shared__ float Xs[16][128];
    float acc[8][8];
    #pragma unroll
    for(int i=0;i<8;i++){ 
        #pragma unroll
        for(int j=0;j<8;j++) acc[i][j]=0.f; }

    int tid = threadIdx.x;
    int lm = tid >> 1, lk8 = (tid & 1) * 8;
    int xk = tid >> 4, xn8 = (tid & 15) * 8;
    int tmr = (tid >> 4) * 8, tnr = (tid & 15) * 8;

    for(int k0 = 0; k0 < CC; k0 += 16){
        float4 w0 = *(const float4*)&W[(m0+lm)*CC + k0 + lk8];
        float4 w1 = *(const float4*)&W[(m0+lm)*CC + k0 + lk8 + 4];
        Ws[lk8+0][lm]=w0.x; Ws[lk8+1][lm]=w0.y; Ws[lk8+2][lm]=w0.z; Ws[lk8+3][lm]=w0.w;
        Ws[lk8+4][lm]=w1.x; Ws[lk8+5][lm]=w1.y; Ws[lk8+6][lm]=w1.z; Ws[lk8+7][lm]=w1.w;
        const float* src = X + (size_t)(k0+xk)*HW + n0 + xn8;
        *(float4*)&Xs[xk][xn8]   = *(const float4*)(src);
        *(float4*)&Xs[xk][xn8+4] = *(const float4*)(src+4);
        __syncthreads();
        #pragma unroll
        for(int k = 0; k < 16; k++){
            float a[8], xr[8];
            *(float4*)&a[0] = *(float4*)&Ws[k][tmr];
            *(float4*)&a[4] = *(float4*)&Ws[k][tmr+4];
            *(float4*)&xr[0] = *(float4*)&Xs[k][tnr];
            *(float4*)&xr[4] = *(float4*)&Xs[k][tnr+4];
            #pragma unroll
            for(int i=0;i<8;i++)
                #pragma unroll
                for(int j=0;j<8;j++) acc[i][j] += a[i]*xr[j];
        }
        __syncthreads();
    }
    #pragma unroll
    for(int i = 0; i < 8; i++){
        int oc = m0 + tmr + i;
        float bi = bias[oc];
        float* op = O + (size_t)oc*HW + n0 + tnr;
        #pragma unroll
        for(int j = 0; j < 8; j++) op[j] = acc[i][j] + bi;
    }
}

// stage 5: tiny attention over S=3, per (pixel, head)
__global__ void k_attn(){
    int n = blockIdx.x * blockDim.x + threadIdx.x;   // 0..16383 (token)
    int head = blockIdx.y;
    int b = n >> 12, p = n & 4095;
    int off0 = ((0*BB+b)*CC)*HW + p;
    int off1 = ((1*BB+b)*CC)*HW + p;
    int off2 = ((2*BB+b)*CC)*HW + p;
    int cbase = head * HDd;

    float sc[3][3];
    #pragma unroll
    for(int i=0;i<3;i++){ 
        #pragma unroll
        for(int j=0;j<3;j++) sc[i][j]=0.f; }

    #pragma unroll 8
    for(int d = 0; d < HDd; d++){
        int co = (cbase + d) * HW;
        float q0=g_qt[off0+co], q1=g_qt[off1+co], q2=g_qt[off2+co];
        float k0=g_kt[off0+co], k1=g_kt[off1+co], k2=g_kt[off2+co];
        sc[0][0]+=q0*k0; sc[0][1]+=q0*k1; sc[0][2]+=q0*k2;
        sc[1][0]+=q1*k0; sc[1][1]+=q1*k1; sc[1][2]+=q1*k2;
        sc[2][0]+=q2*k0; sc[2][1]+=q2*k1; sc[2][2]+=q2*k2;
    }
    const float scale = 0.17677669529663688f;   // 1/sqrt(32)
    float at[3][3];
    #pragma unroll
    for(int s_ = 0; s_ < 3; s_++){
        float a0 = sc[s_][0]*scale, a1 = sc[s_][1]*scale, a2 = sc[s_][2]*scale;
        float m = fmaxf(a0, fmaxf(a1, a2));
        float e0 = expf(a0-m), e1 = expf(a1-m), e2 = expf(a2-m);
        float inv = 1.0f / (e0+e1+e2);
        at[s_][0]=e0*inv; at[s_][1]=e1*inv; at[s_][2]=e2*inv;
    }
    #pragma unroll 8
    for(int d = 0; d < HDd; d++){
        int co = (cbase + d) * HW;
        float v0=g_vt[off0+co], v1=g_vt[off1+co], v2=g_vt[off2+co];
        g_o[off0+co] = at[0][0]*v0 + at[0][1]*v1 + at[0][2]*v2;
        g_o[off1+co] = at[1][0]*v0 + at[1][1]*v1 + at[1][2]*v2;
        g_o[off2+co] = at[2][0]*v0 + at[2][1]*v1 + at[2][2]*v2;
    }
}

// stage 6: attn_out GEMM fused with softmax-weighted s-combine (K=768)
__global__ __launch_bounds__(256,2) void k_out(const float* __restrict__ Wo,
                                               const float* __restrict__ bo)
{
    int b = blockIdx.z;
    int m0 = blockIdx.y * 128;
    int n0 = blockIdx.x * 128;
    float wmix[3] = { g_wmix[b*3+0], g_wmix[b*3+1], g_wmix[b*3+2] };

    __shared__ float Ws[16][128];
    __shared__ float Xs[16][128];
    float acc[8][8];
    #pragma unroll
    for(int i=0;i<8;i++){ 
        #pragma unroll
        for(int j=0;j<8;j++) acc[i][j]=0.f; }

    int tid = threadIdx.x;
    int lm = tid >> 1, lk8 = (tid & 1) * 8;
    int xk = tid >> 4, xn8 = (tid & 15) * 8;
    int tmr = (tid >> 4) * 8, tnr = (tid & 15) * 8;

    for(int k0 = 0; k0 < SS*CC; k0 += 16){
        int s  = k0 >> 8;
        int cb = k0 & 255;
        float4 w0 = *(const float4*)&Wo[(m0+lm)*CC + cb + lk8];
        float4 w1 = *(const float4*)&Wo[(m0+lm)*CC + cb + lk8 + 4];
        Ws[lk8+0][lm]=w0.x; Ws[lk8+1][lm]=w0.y; Ws[lk8+2][lm]=w0.z; Ws[lk8+3][lm]=w0.w;
        Ws[lk8+4][lm]=w1.x; Ws[lk8+5][lm]=w1.y; Ws[lk8+6][lm]=w1.z; Ws[lk8+7][lm]=w1.w;
        float scl = wmix[s];
        const float* src = g_o + (size_t)((s*BB+b)*CC + cb + xk)*HW + n0 + xn8;
        float4 x0 = *(const float4*)(src);
        float4 x1 = *(const float4*)(src+4);
        x0.x*=scl; x0.y*=scl; x0.z*=scl; x0.w*=scl;
        x1.x*=scl; x1.y*=scl; x1.z*=scl; x1.w*=scl;
        *(float4*)&Xs[xk][xn8]   = x0;
        *(float4*)&Xs[xk][xn8+4] = x1;
        __syncthreads();
        #pragma unroll
        for(int k = 0; k < 16; k++){
            float a[8], xr[8];
            *(float4*)&a[0] = *(float4*)&Ws[k][tmr];
            *(float4*)&a[4] = *(float4*)&Ws[k][tmr+4];
            *(float4*)&xr[0] = *(float4*)&Xs[k][tnr];
            *(float4*)&xr[4] = *(float4*)&Xs[k][tnr+4];
            #pragma unroll
            for(int i=0;i<8;i++)
                #pragma unroll
                for(int j=0;j<8;j++) acc[i][j] += a[i]*xr[j];
        }
        __syncthreads();
    }
    #pragma unroll
    for(int i = 0; i < 8; i++){
        int oc = m0 + tmr + i;
        float bi = bo[oc];
        float* op = g_integr + (size_t)(b*CC+oc)*HW + n0 + tnr;
        #pragma unroll
        for(int j = 0; j < 8; j++) op[j] = acc[i][j] + bi;
    }
}

// stage 7: 3x3 conv as K=2304 GEMM + bias + BN + gelu
__global__ __launch_bounds__(256,2) void k_conv(const float* __restrict__ Wc,
                                                const float* __restrict__ b1,
                                                const float* __restrict__ opbn)
{
    int b = blockIdx.z;
    int m0 = blockIdx.y * 128;
    int n0 = blockIdx.x * 128;

    __shared__ float Ws[16][128];
    __shared__ float Xs[16][128];
    float acc[8][8];
    #pragma unroll
    for(int i=0;i<8;i++){ 
        #pragma unroll
        for(int j=0;j<8;j++) acc[i][j]=0.f; }

    int tid = threadIdx.x;
    int lm = tid >> 1, lk8 = (tid & 1) * 8;
    int xk = tid >> 4, xn8 = (tid & 15) * 8;
    int tmr = (tid >> 4) * 8, tnr = (tid & 15) * 8;

    for(int k0 = 0; k0 < CC*9; k0 += 16){
        float4 w0 = *(const float4*)&Wc[(m0+lm)*(CC*9) + k0 + lk8];
        float4 w1 = *(const float4*)&Wc[(m0+lm)*(CC*9) + k0 + lk8 + 4];
        Ws[lk8+0][lm]=w0.x; Ws[lk8+1][lm]=w0.y; Ws[lk8+2][lm]=w0.z; Ws[lk8+3][lm]=w0.w;
        Ws[lk8+4][lm]=w1.x; Ws[lk8+5][lm]=w1.y; Ws[lk8+6][lm]=w1.z; Ws[lk8+7][lm]=w1.w;
        int kk = k0 + xk;
        int c = kk / 9; int r = kk - c*9; int kh = r / 3; int kw = r - kh*3;
        const float* src = g_integr + (size_t)(b*CC + c)*HW;
        #pragma unroll
        for(int j = 0; j < 8; j++){
            int pix = n0 + xn8 + j;
            int hh = (pix >> 6) + kh - 1;
            int ww = (pix & 63) + kw - 1;
            float v = 0.f;
            if((unsigned)hh < 64u && (unsigned)ww < 64u) v = src[hh*64 + ww];
            Xs[xk][xn8+j] = v;
        }
        __syncthreads();
        #pragma unroll
        for(int k = 0; k < 16; k++){
            float a[8], xr[8];
            *(float4*)&a[0] = *(float4*)&Ws[k][tmr];
            *(float4*)&a[4] = *(float4*)&Ws[k][tmr+4];
            *(float4*)&xr[0] = *(float4*)&Xs[k][tnr];
            *(float4*)&xr[4] = *(float4*)&Xs[k][tnr+4];
            #pragma unroll
            for(int i=0;i<8;i++)
                #pragma unroll
                for(int j=0;j<8;j++) acc[i][j] += a[i]*xr[j];
        }
        __syncthreads();
    }
    #pragma unroll
    for(int i = 0; i < 8; i++){
        int oc = m0 + tmr + i;
        float g  = opbn[0*CC+oc];
        float be = opbn[1*CC+oc];
        float mu = opbn[2*CC+oc];
        float vr = opbn[3*CC+oc];
        float sc = g * rsqrtf(vr + EPSf);
        float bi = b1[oc];
        float* op = g_y2 + (size_t)(b*CC+oc)*HW + n0 + tnr;
        #pragma unroll
        for(int j = 0; j < 8; j++){
            float y = acc[i][j] + bi;
            y = (y - mu)*sc + be;
            op[j] = gelu_f(y);
        }
    }
}

// stage 8: final 1x1 GEMM + bias + residual (x[1])
__global__ __launch_bounds__(256,2) void k_final(const float* __restrict__ W2,
                                                 const float* __restrict__ b2,
                                                 const float* __restrict__ x,
                                                 float* __restrict__ out)
{
    int b = blockIdx.z;
    int m0 = blockIdx.y * 128;
    int n0 = blockIdx.x * 128;

    __shared__ float Ws[16][128];
    __shared__ float Xs[16][128];
    float acc[8][8];
    #pragma unroll
    for(int i=0;i<8;i++){ 
        #pragma unroll
        for(int j=0;j<8;j++) acc[i][j]=0.f; }

    int tid = threadIdx.x;
    int lm = tid >> 1, lk8 = (tid & 1) * 8;
    int xk = tid >> 4, xn8 = (tid & 15) * 8;
    int tmr = (tid >> 4) * 8, tnr = (tid & 15) * 8;

    for(int k0 = 0; k0 < CC; k0 += 16){
        float4 w0 = *(const float4*)&W2[(m0+lm)*CC + k0 + lk8];
        float4 w1 = *(const float4*)&W2[(m0+lm)*CC + k0 + lk8 + 4];
        Ws[lk8+0][lm]=w0.x; Ws[lk8+1][lm]=w0.y; Ws[lk8+2][lm]=w0.z; Ws[lk8+3][lm]=w0.w;
        Ws[lk8+4][lm]=w1.x; Ws[lk8+5][lm]=w1.y; Ws[lk8+6][lm]=w1.z; Ws[lk8+7][lm]=w1.w;
        const float* src = g_y2 + (size_t)(b*CC + k0 + xk)*HW + n0 + xn8;
        *(float4*)&Xs[xk][xn8]   = *(const float4*)(src);
        *(float4*)&Xs[xk][xn8+4] = *(const float4*)(src+4);
        __syncthreads();
        #pragma unroll
        for(int k = 0; k < 16; k++){
            float a[8], xr[8];
            *(float4*)&a[0] = *(float4*)&Ws[k][tmr];
            *(float4*)&a[4] = *(float4*)&Ws[k][tmr+4];
            *(float4*)&xr[0] = *(float4*)&Xs[k][tnr];
            *(float4*)&xr[4] = *(float4*)&Xs[k][tnr+4];
            #pragma unroll
            for(int i=0;i<8;i++)
                #pragma unroll
                for(int j=0;j<8;j++) acc[i][j] += a[i]*xr[j];
        }
        __syncthreads();
    }
    #pragma unroll
    for(int i = 0; i < 8; i++){
        int oc = m0 + tmr + i;
        float bi = b2[oc];
        const float* resid = x + (size_t)((1*BB+b)*CC + oc)*HW + n0 + tnr;
        float* op = out + (size_t)(b*CC+oc)*HW + n0 + tnr;
        #pragma unroll
        for(int j = 0; j < 8; j++) op[j] = acc[i][j] + bi + resid[j];
    }
}

// ---------------- launcher --------------------------------------------------
extern "C" void kernel_launch(void* const* d_in, const int* in_sizes, int n_in,
                              void* d_out, int out_size)
{
    (void)in_sizes; (void)n_in; (void)out_size;
    const float* x   = (const float*)d_in[0];
    const float* Wq  = (const float*)d_in[1];
    const float* bq  = (const float*)d_in[2];
    const float* bnq = (const float*)d_in[3];
    const float* Wk_ = (const float*)d_in[4];
    const float* bk_ = (const float*)d_in[5];
    const float* bnk = (const float*)d_in[6];
    const float* Wv  = (const float*)d_in[7];
    const float* bv  = (const float*)d_in[8];
    const float* bnv = (const float*)d_in[9];
    const float* iw1 = (const float*)d_in[10];
    const float* ib1 = (const float*)d_in[11];
    const float* iw2 = (const float*)d_in[12];
    const float* ib2 = (const float*)d_in[13];
    const float* aiw = (const float*)d_in[14];
    const float* aib = (const float*)d_in[15];
    const float* aow = (const float*)d_in[16];
    const float* aob = (const float*)d_in[17];
    const float* cw  = (const float*)d_in[18];
    const float* cb1 = (const float*)d_in[19];
    const float* cbn = (const float*)d_in[20];
    const float* w2  = (const float*)d_in[21];
    const float* b2  = (const float*)d_in[22];
    float* out = (float*)d_out;

    k_pool<<<SS*BB*CC, 256>>>(x);
    k_imp<<<1, 256>>>(iw1, ib1, iw2, ib2);
    k_proj<<<dim3(32,2,36), 256>>>(x, Wq,bq,bnq, Wk_,bk_,bnk, Wv,bv,bnv);
    k_attnin<<<dim3(32,2,36), 256>>>(aiw, aib);
    k_attn<<<dim3(64,8), 256>>>();
    k_out<<<dim3(32,2,4), 256>>>(aow, aob);
    k_conv<<<dim3(32,2,4), 256>>>(cw, cb1, cbn);
    k_final<<<dim3(32,2,4), 256>>>(w2, b2, x, out);
}

// round 3
// speedup vs baseline: 1.7938x; 1.7938x over previous
#include <cuda_runtime.h>
#include <cstdint>
#include <math.h>

#define SS 3
#define BB 4
#define CC 256
#define HW 4096
#define EPSf 1e-5f

// ---------------- scratch ----------------------------------------------------
__device__ float g_pooled[BB*SS*CC];
__device__ float g_wmix[BB*SS];
__device__ float g_q [SS*BB*CC*HW];
__device__ float g_k [SS*BB*CC*HW];
__device__ float g_v [SS*BB*CC*HW];
__device__ float g_qt[SS*BB*CC*HW];
__device__ float g_kt[SS*BB*CC*HW];
__device__ float g_vt[SS*BB*CC*HW];
__device__ float g_o [SS*BB*CC*HW];
__device__ float g_integr[BB*CC*HW];
__device__ float g_y2[BB*CC*HW];

__device__ __forceinline__ float gelu_f(float x){
    return 0.5f * x * (1.0f + erff(x * 0.70710678118654752f));
}
__device__ __forceinline__ uint32_t f2tf(float x){
    uint32_t r;
    asm("cvt.rna.tf32.f32 %0, %1;" : "=r"(r) : "f"(x));
    return r;
}
__device__ __forceinline__ void mma8(float c[4], const uint32_t a[4], const uint32_t b[2]){
    asm volatile(
        "mma.sync.aligned.m16n8k8.row.col.f32.tf32.tf32.f32 "
        "{%0,%1,%2,%3}, {%4,%5,%6,%7}, {%8,%9}, {%0,%1,%2,%3};"
        : "+f"(c[0]), "+f"(c[1]), "+f"(c[2]), "+f"(c[3])
        : "r"(a[0]), "r"(a[1]), "r"(a[2]), "r"(a[3]), "r"(b[0]), "r"(b[1]));
}

// ---------------- GEMM building blocks ---------------------------------------
// CTA tile 128x128, BK=32, 256 threads = 8 warps (2 M x 4 N), warp tile 64x32.
// Smem: As[k][ (m+8k)&127 ], Bs[k][ (n+8k)&127 ]  (tf32 bit patterns)

// A loader: weights W row-major [m][k], lda given. tile rows m0..m0+127, cols k0..k0+31.
__device__ __forceinline__ void ldA(uint32_t* As, const float* Wt, int lda, int tid){
    int m = tid >> 1, kh = (tid & 1) * 16;
    const float4* s = (const float4*)(Wt + (size_t)m*lda + kh);
    float4 v0 = s[0], v1 = s[1], v2 = s[2], v3 = s[3];
    float vals[16] = {v0.x,v0.y,v0.z,v0.w, v1.x,v1.y,v1.z,v1.w,
                      v2.x,v2.y,v2.z,v2.w, v3.x,v3.y,v3.z,v3.w};
    #pragma unroll
    for(int i = 0; i < 16; i++){
        int k = kh + i;
        As[k*128 + ((m + 8*k) & 127)] = f2tf(vals[i]);
    }
}

// B loader: activations X[k][n] with row stride `stride`, tile k0..k0+31 x n0..n0+127
__device__ __forceinline__ void ldB(uint32_t* Bs, const float* Xt, int stride, int tid, float scl){
    int k = tid >> 3, nb = (tid & 7) * 16;
    const float4* s = (const float4*)(Xt + (size_t)k*stride + nb);
    float4 v0 = s[0], v1 = s[1], v2 = s[2], v3 = s[3];
    float vals[16] = {v0.x,v0.y,v0.z,v0.w, v1.x,v1.y,v1.z,v1.w,
                      v2.x,v2.y,v2.z,v2.w, v3.x,v3.y,v3.z,v3.w};
    #pragma unroll
    for(int i = 0; i < 16; i++){
        int n = nb + i;
        Bs[k*128 + ((n + 8*k) & 127)] = f2tf(vals[i] * scl);
    }
}

__device__ __forceinline__ void mma_compute(const uint32_t* As, const uint32_t* Bs,
                                            float acc[4][4][4], int warp_m, int warp_n, int lane){
    int g = lane >> 2, tg = lane & 3;
    #pragma unroll
    for(int ks = 0; ks < 4; ks++){
        int kk = ks*8;
        int ka = kk + tg, kb = kk + tg + 4;
        uint32_t a[4][4], bf[4][2];
        #pragma unroll
        for(int mi = 0; mi < 4; mi++){
            int m = warp_m*64 + mi*16 + g;
            a[mi][0] = As[ka*128 + ((m     + 8*ka) & 127)];
            a[mi][1] = As[ka*128 + ((m + 8 + 8*ka) & 127)];
            a[mi][2] = As[kb*128 + ((m     + 8*kb) & 127)];
            a[mi][3] = As[kb*128 + ((m + 8 + 8*kb) & 127)];
        }
        #pragma unroll
        for(int ni = 0; ni < 4; ni++){
            int n = warp_n*32 + ni*8 + g;
            bf[ni][0] = Bs[ka*128 + ((n + 8*ka) & 127)];
            bf[ni][1] = Bs[kb*128 + ((n + 8*kb) & 127)];
        }
        #pragma unroll
        for(int mi = 0; mi < 4; mi++)
            #pragma unroll
            for(int ni = 0; ni < 4; ni++)
                mma8(acc[mi][ni], a[mi], bf[ni]);
    }
}

#define GEMM_PRE() \
    __shared__ uint32_t As[32*128]; \
    __shared__ uint32_t Bs[32*128]; \
    float acc[4][4][4]; \
    _Pragma("unroll") \
    for(int i=0;i<4;i++) _Pragma("unroll") for(int j=0;j<4;j++) _Pragma("unroll") for(int r=0;r<4;r++) acc[i][j][r]=0.f; \
    int tid = threadIdx.x; \
    int wid = tid >> 5, lane = tid & 31; \
    int warp_m = wid >> 2, warp_n = wid & 3; \
    int g = lane >> 2, tg = lane & 3;

// ---------------- stage 1: spatial mean pool --------------------------------
__global__ void k_pool(const float* __restrict__ x){
    int id = blockIdx.x;
    int c = id & 255;
    int b = (id >> 8) & 3;
    int s = id >> 10;
    const float* p = x + (size_t)((s*BB+b)*CC + c) * HW;
    float sum = 0.f;
    for(int i = threadIdx.x; i < HW; i += 256) sum += p[i];
    __shared__ float red[8];
    #pragma unroll
    for(int o = 16; o > 0; o >>= 1) sum += __shfl_down_sync(0xffffffffu, sum, o);
    if((threadIdx.x & 31) == 0) red[threadIdx.x >> 5] = sum;
    __syncthreads();
    if(threadIdx.x == 0){
        float t = 0.f;
        #pragma unroll
        for(int i = 0; i < 8; i++) t += red[i];
        g_pooled[(b*SS + s)*CC + c] = t * (1.0f / HW);
    }
}

// ---------------- stage 2: importance MLP + softmax --------------------------
__global__ void k_imp(const float* __restrict__ iw1, const float* __restrict__ ib1,
                      const float* __restrict__ iw2, const float* __restrict__ ib2){
    __shared__ float h[BB][CC];
    __shared__ float lg[BB][SS];
    int t = threadIdx.x;
    for(int b = 0; b < BB; b++){
        float acc = ib1[t];
        const float4* pw = (const float4*)(iw1 + t * (SS*CC));
        const float4* pp = (const float4*)(g_pooled + b * (SS*CC));
        #pragma unroll 4
        for(int i = 0; i < (SS*CC)/4; i++){
            float4 a = pw[i], c = pp[i];
            acc += a.x*c.x + a.y*c.y + a.z*c.z + a.w*c.w;
        }
        h[b][t] = gelu_f(acc);
    }
    __syncthreads();
    if(t < BB*SS){
        int b = t / SS, s = t % SS;
        float acc = ib2[s];
        for(int c = 0; c < CC; c++) acc += h[b][c] * iw2[s*CC + c];
        lg[b][s] = acc;
    }
    __syncthreads();
    if(t < BB){
        float m  = fmaxf(lg[t][0], fmaxf(lg[t][1], lg[t][2]));
        float e0 = expf(lg[t][0]-m), e1 = expf(lg[t][1]-m), e2 = expf(lg[t][2]-m);
        float inv = 1.0f / (e0 + e1 + e2);
        g_wmix[t*SS+0] = e0*inv; g_wmix[t*SS+1] = e1*inv; g_wmix[t*SS+2] = e2*inv;
    }
}

// ---------------- stage 3: q/k/v projection ----------------------------------
__global__ __launch_bounds__(256,2) void k_projT(
    const float* __restrict__ x,
    const float* __restrict__ Wq, const float* __restrict__ bq, const float* __restrict__ bnq,
    const float* __restrict__ Wk_, const float* __restrict__ bk_, const float* __restrict__ bnk,
    const float* __restrict__ Wv, const float* __restrict__ bv, const float* __restrict__ bnv)
{
    int z = blockIdx.z;
    int which = z / 12;
    int s = (z % 12) >> 2;
    int b = z & 3;
    const float *W, *bias, *bn; float* out;
    if(which == 0){ W = Wq;  bias = bq;  bn = bnq; out = g_q; }
    else if(which == 1){ W = Wk_; bias = bk_; bn = bnk; out = g_k; }
    else { W = Wv; bias = bv; bn = bnv; out = g_v; }
    W += s * CC * CC;
    const float* X = x   + (size_t)(s*BB+b)*CC*HW;
    float*       O = out + (size_t)(s*BB+b)*CC*HW;
    int m0 = blockIdx.y * 128;
    int n0 = blockIdx.x * 128;

    GEMM_PRE();
    for(int k0 = 0; k0 < CC; k0 += 32){
        ldA(As, W + (size_t)m0*CC + k0, CC, tid);
        ldB(Bs, X + (size_t)k0*HW + n0, HW, tid, 1.0f);
        __syncthreads();
        mma_compute(As, Bs, acc, warp_m, warp_n, lane);
        __syncthreads();
    }
    #pragma unroll
    for(int mi = 0; mi < 4; mi++){
        int r0 = m0 + warp_m*64 + mi*16 + g;
        int r1 = r0 + 8;
        float sc0 = bn[(s*4+0)*CC+r0] * rsqrtf(bn[(s*4+3)*CC+r0] + EPSf);
        float sc1 = bn[(s*4+0)*CC+r1] * rsqrtf(bn[(s*4+3)*CC+r1] + EPSf);
        float be0 = bn[(s*4+1)*CC+r0], be1 = bn[(s*4+1)*CC+r1];
        float mu0 = bn[(s*4+2)*CC+r0], mu1 = bn[(s*4+2)*CC+r1];
        float bi0 = bias[s*CC+r0], bi1 = bias[s*CC+r1];
        #pragma unroll
        for(int ni = 0; ni < 4; ni++){
            int nc = n0 + warp_n*32 + ni*8 + tg*2;
            float2 o0, o1;
            o0.x = gelu_f((acc[mi][ni][0] + bi0 - mu0)*sc0 + be0);
            o0.y = gelu_f((acc[mi][ni][1] + bi0 - mu0)*sc0 + be0);
            o1.x = gelu_f((acc[mi][ni][2] + bi1 - mu1)*sc1 + be1);
            o1.y = gelu_f((acc[mi][ni][3] + bi1 - mu1)*sc1 + be1);
            *(float2*)&O[(size_t)r0*HW + nc] = o0;
            *(float2*)&O[(size_t)r1*HW + nc] = o1;
        }
    }
}

// ---------------- stage 4: attn_in projection --------------------------------
__global__ __launch_bounds__(256,2) void k_attninT(const float* __restrict__ aiw,
                                                   const float* __restrict__ aib)
{
    int z = blockIdx.z;
    int which = z / 12;
    int s = (z % 12) >> 2;
    int b = z & 3;
    const float* W = aiw + which * CC * CC;
    const float* bias = aib + which * CC;
    const float* Xg; float* Og;
    if(which == 0){ Xg = g_q; Og = g_qt; }
    else if(which == 1){ Xg = g_k; Og = g_kt; }
    else { Xg = g_v; Og = g_vt; }
    const float* X = Xg + (size_t)(s*BB+b)*CC*HW;
    float*       O = Og + (size_t)(s*BB+b)*CC*HW;
    int m0 = blockIdx.y * 128;
    int n0 = blockIdx.x * 128;

    GEMM_PRE();
    for(int k0 = 0; k0 < CC; k0 += 32){
        ldA(As, W + (size_t)m0*CC + k0, CC, tid);
        ldB(Bs, X + (size_t)k0*HW + n0, HW, tid, 1.0f);
        __syncthreads();
        mma_compute(As, Bs, acc, warp_m, warp_n, lane);
        __syncthreads();
    }
    #pragma unroll
    for(int mi = 0; mi < 4; mi++){
        int r0 = m0 + warp_m*64 + mi*16 + g;
        int r1 = r0 + 8;
        float bi0 = bias[r0], bi1 = bias[r1];
        #pragma unroll
        for(int ni = 0; ni < 4; ni++){
            int nc = n0 + warp_n*32 + ni*8 + tg*2;
            float2 o0, o1;
            o0.x = acc[mi][ni][0] + bi0; o0.y = acc[mi][ni][1] + bi0;
            o1.x = acc[mi][ni][2] + bi1; o1.y = acc[mi][ni][3] + bi1;
            *(float2*)&O[(size_t)r0*HW + nc] = o0;
            *(float2*)&O[(size_t)r1*HW + nc] = o1;
        }
    }
}

// ---------------- stage 5: tiny attention over S=3 ---------------------------
__global__ void k_attn(){
    int n = blockIdx.x * blockDim.x + threadIdx.x;
    int head = blockIdx.y;
    int b = n >> 12, p = n & 4095;
    int off0 = ((0*BB+b)*CC)*HW + p;
    int off1 = ((1*BB+b)*CC)*HW + p;
    int off2 = ((2*BB+b)*CC)*HW + p;
    int cbase = head * 32;

    float sc[3][3];
    #pragma unroll
    for(int i=0;i<3;i++){
        #pragma unroll
        for(int j=0;j<3;j++) sc[i][j]=0.f; }

    #pragma unroll 8
    for(int d = 0; d < 32; d++){
        int co = (cbase + d) * HW;
        float q0=g_qt[off0+co], q1=g_qt[off1+co], q2=g_qt[off2+co];
        float k0=g_kt[off0+co], k1=g_kt[off1+co], k2=g_kt[off2+co];
        sc[0][0]+=q0*k0; sc[0][1]+=q0*k1; sc[0][2]+=q0*k2;
        sc[1][0]+=q1*k0; sc[1][1]+=q1*k1; sc[1][2]+=q1*k2;
        sc[2][0]+=q2*k0; sc[2][1]+=q2*k1; sc[2][2]+=q2*k2;
    }
    const float scale = 0.17677669529663688f;
    float at[3][3];
    #pragma unroll
    for(int s_ = 0; s_ < 3; s_++){
        float a0 = sc[s_][0]*scale, a1 = sc[s_][1]*scale, a2 = sc[s_][2]*scale;
        float m = fmaxf(a0, fmaxf(a1, a2));
        float e0 = expf(a0-m), e1 = expf(a1-m), e2 = expf(a2-m);
        float inv = 1.0f / (e0+e1+e2);
        at[s_][0]=e0*inv; at[s_][1]=e1*inv; at[s_][2]=e2*inv;
    }
    #pragma unroll 8
    for(int d = 0; d < 32; d++){
        int co = (cbase + d) * HW;
        float v0=g_vt[off0+co], v1=g_vt[off1+co], v2=g_vt[off2+co];
        g_o[off0+co] = at[0][0]*v0 + at[0][1]*v1 + at[0][2]*v2;
        g_o[off1+co] = at[1][0]*v0 + at[1][1]*v1 + at[1][2]*v2;
        g_o[off2+co] = at[2][0]*v0 + at[2][1]*v1 + at[2][2]*v2;
    }
}

// ---------------- stage 6: attn_out + weighted s-combine (K=768) -------------
__global__ __launch_bounds__(256,2) void k_outT(const float* __restrict__ Wo,
                                                const float* __restrict__ bo)
{
    int b = blockIdx.z;
    int m0 = blockIdx.y * 128;
    int n0 = blockIdx.x * 128;

    GEMM_PRE();
    for(int k0 = 0; k0 < SS*CC; k0 += 32){
        int s  = k0 >> 8;
        int cb2 = k0 & 255;
        float scl = g_wmix[b*3 + s];
        ldA(As, Wo + (size_t)m0*CC + cb2, CC, tid);
        ldB(Bs, g_o + (size_t)((s*BB+b)*CC + cb2)*HW + n0, HW, tid, scl);
        __syncthreads();
        mma_compute(As, Bs, acc, warp_m, warp_n, lane);
        __syncthreads();
    }
    #pragma unroll
    for(int mi = 0; mi < 4; mi++){
        int r0 = m0 + warp_m*64 + mi*16 + g;
        int r1 = r0 + 8;
        float bi0 = bo[r0], bi1 = bo[r1];
        #pragma unroll
        for(int ni = 0; ni < 4; ni++){
            int nc = n0 + warp_n*32 + ni*8 + tg*2;
            float2 o0, o1;
            o0.x = acc[mi][ni][0] + bi0; o0.y = acc[mi][ni][1] + bi0;
            o1.x = acc[mi][ni][2] + bi1; o1.y = acc[mi][ni][3] + bi1;
            *(float2*)&g_integr[(size_t)(b*CC+r0)*HW + nc] = o0;
            *(float2*)&g_integr[(size_t)(b*CC+r1)*HW + nc] = o1;
        }
    }
}

// ---------------- stage 7: 3x3 conv as GEMM (K=2304) -------------------------
__global__ __launch_bounds__(256,2) void k_convT(const float* __restrict__ Wc,
                                                 const float* __restrict__ b1,
                                                 const float* __restrict__ opbn)
{
    int b = blockIdx.z;
    int m0 = blockIdx.y * 128;
    int n0 = blockIdx.x * 128;

    GEMM_PRE();
    for(int k0 = 0; k0 < CC*9; k0 += 32){
        ldA(As, Wc + (size_t)m0*(CC*9) + k0, CC*9, tid);
        {
            int k = tid >> 3, nb = (tid & 7) * 16;
            int kkg = k0 + k;
            int c  = kkg / 9;
            int r9 = kkg - c*9;
            int kh = r9 / 3, kw = r9 - kh*3;
            const float* src = g_integr + (size_t)(b*CC + c)*HW;
            #pragma unroll
            for(int j = 0; j < 16; j++){
                int pix = n0 + nb + j;
                int hh = (pix >> 6) + kh - 1;
                int ww = (pix & 63) + kw - 1;
                float v = 0.f;
                if((unsigned)hh < 64u && (unsigned)ww < 64u) v = src[hh*64 + ww];
                Bs[k*128 + ((nb + j + 8*k) & 127)] = f2tf(v);
            }
        }
        __syncthreads();
        mma_compute(As, Bs, acc, warp_m, warp_n, lane);
        __syncthreads();
    }
    #pragma unroll
    for(int mi = 0; mi < 4; mi++){
        int r0 = m0 + warp_m*64 + mi*16 + g;
        int r1 = r0 + 8;
        float sc0 = opbn[0*CC+r0] * rsqrtf(opbn[3*CC+r0] + EPSf);
        float sc1 = opbn[0*CC+r1] * rsqrtf(opbn[3*CC+r1] + EPSf);
        float be0 = opbn[1*CC+r0], be1 = opbn[1*CC+r1];
        float mu0 = opbn[2*CC+r0], mu1 = opbn[2*CC+r1];
        float bi0 = b1[r0], bi1 = b1[r1];
        #pragma unroll
        for(int ni = 0; ni < 4; ni++){
            int nc = n0 + warp_n*32 + ni*8 + tg*2;
            float2 o0, o1;
            o0.x = gelu_f((acc[mi][ni][0] + bi0 - mu0)*sc0 + be0);
            o0.y = gelu_f((acc[mi][ni][1] + bi0 - mu0)*sc0 + be0);
            o1.x = gelu_f((acc[mi][ni][2] + bi1 - mu1)*sc1 + be1);
            o1.y = gelu_f((acc[mi][ni][3] + bi1 - mu1)*sc1 + be1);
            *(float2*)&g_y2[(size_t)(b*CC+r0)*HW + nc] = o0;
            *(float2*)&g_y2[(size_t)(b*CC+r1)*HW + nc] = o1;
        }
    }
}

// ---------------- stage 8: final 1x1 + residual ------------------------------
__global__ __launch_bounds__(256,2) void k_finalT(const float* __restrict__ W2,
                                                  const float* __restrict__ b2,
                                                  const float* __restrict__ x,
                                                  float* __restrict__ out)
{
    int b = blockIdx.z;
    int m0 = blockIdx.y * 128;
    int n0 = blockIdx.x * 128;

    GEMM_PRE();
    for(int k0 = 0; k0 < CC; k0 += 32){
        ldA(As, W2 + (size_t)m0*CC + k0, CC, tid);
        ldB(Bs, g_y2 + (size_t)(b*CC + k0)*HW + n0, HW, tid, 1.0f);
        __syncthreads();
        mma_compute(As, Bs, acc, warp_m, warp_n, lane);
        __syncthreads();
    }
    #pragma unroll
    for(int mi = 0; mi < 4; mi++){
        int r0 = m0 + warp_m*64 + mi*16 + g;
        int r1 = r0 + 8;
        float bi0 = b2[r0], bi1 = b2[r1];
        const float* res0 = x + (size_t)((1*BB+b)*CC + r0)*HW;
        const float* res1 = x + (size_t)((1*BB+b)*CC + r1)*HW;
        #pragma unroll
        for(int ni = 0; ni < 4; ni++){
            int nc = n0 + warp_n*32 + ni*8 + tg*2;
            float2 a0 = *(const float2*)&res0[nc];
            float2 a1 = *(const float2*)&res1[nc];
            float2 o0, o1;
            o0.x = acc[mi][ni][0] + bi0 + a0.x; o0.y = acc[mi][ni][1] + bi0 + a0.y;
            o1.x = acc[mi][ni][2] + bi1 + a1.x; o1.y = acc[mi][ni][3] + bi1 + a1.y;
            *(float2*)&out[(size_t)(b*CC+r0)*HW + nc] = o0;
            *(float2*)&out[(size_t)(b*CC+r1)*HW + nc] = o1;
        }
    }
}

// ---------------- launcher ---------------------------------------------------
extern "C" void kernel_launch(void* const* d_in, const int* in_sizes, int n_in,
                              void* d_out, int out_size)
{
    (void)in_sizes; (void)n_in; (void)out_size;
    const float* x   = (const float*)d_in[0];
    const float* Wq  = (const float*)d_in[1];
    const float* bq  = (const float*)d_in[2];
    const float* bnq = (const float*)d_in[3];
    const float* Wk_ = (const float*)d_in[4];
    const float* bk_ = (const float*)d_in[5];
    const float* bnk = (const float*)d_in[6];
    const float* Wv  = (const float*)d_in[7];
    const float* bv  = (const float*)d_in[8];
    const float* bnv = (const float*)d_in[9];
    const float* iw1 = (const float*)d_in[10];
    const float* ib1 = (const float*)d_in[11];
    const float* iw2 = (const float*)d_in[12];
    const float* ib2 = (const float*)d_in[13];
    const float* aiw = (const float*)d_in[14];
    const float* aib = (const float*)d_in[15];
    const float* aow = (const float*)d_in[16];
    const float* aob = (const float*)d_in[17];
    const float* cw  = (const float*)d_in[18];
    const float* cb1 = (const float*)d_in[19];
    const float* cbn = (const float*)d_in[20];
    const float* w2  = (const float*)d_in[21];
    const float* b2  = (const float*)d_in[22];
    float* out = (float*)d_out;

    k_pool<<<SS*BB*CC, 256>>>(x);
    k_imp<<<1, 256>>>(iw1, ib1, iw2, ib2);
    k_projT<<<dim3(32,2,36), 256>>>(x, Wq,bq,bnq, Wk_,bk_,bnk, Wv,bv,bnv);
    k_attninT<<<dim3(32,2,36), 256>>>(aiw, aib);
    k_attn<<<dim3(64,8), 256>>>();
    k_outT<<<dim3(32,2,4), 256>>>(aow, aob);
    k_convT<<<dim3(32,2,4), 256>>>(cw, cb1, cbn);
    k_finalT<<<dim3(32,2,4), 256>>>(w2, b2, x, out);
}